// round 5
// baseline (speedup 1.0000x reference)
#include <cuda_runtime.h>
#include <cuda_bf16.h>
#include <cstdint>
#include <cstddef>

#define DI __device__ __forceinline__

static constexpr int A_ATOMS = 256;
static constexpr int DIN     = 39;   // input features; col 39 = bias (1.0)
static constexpr int HID     = 50;   // hidden; layer-2 bias at col 50

// ---- dynamic smem layout (tiles are 128B-stride SW128-swizzled) ----
static constexpr int SM_W3   = 0;                   // 64 floats (zero-padded)
static constexpr int SM_B3   = 64 * 4;              // 1 float
static constexpr int SM_AH   = 1024;                // 128 rows x 128B  (X hi)
static constexpr int SM_AL   = SM_AH  + 16384;      // X lo
static constexpr int SM_B1H  = SM_AL  + 16384;      // 64 rows x 128B
static constexpr int SM_B1L  = SM_B1H + 8192;
static constexpr int SM_B2H  = SM_B1L + 8192;
static constexpr int SM_B2L  = SM_B2H + 8192;
static constexpr int SM_TOTAL = SM_B2L + 8192;      // 66560 B -> ~3 CTAs/SM

DI uint32_t swz(uint32_t off) { return off ^ ((off >> 3) & 0x70); }

DI float fsilu(float x) {
    float e, r;
    asm("ex2.approx.f32 %0, %1;" : "=f"(e) : "f"(x * -1.4426950408889634f));
    asm("rcp.approx.f32 %0, %1;" : "=f"(r) : "f"(e + 1.0f));
    return x * r;   // x * sigmoid(x)
}

// split v into bf16 hi + bf16 lo, store into two swizzled tiles at (row, col)
DI void st_split(char* hi, char* lo, int row, int k, float v) {
    __nv_bfloat16 h = __float2bfloat16(v);
    float hf = __bfloat162float(h);
    __nv_bfloat16 l = __float2bfloat16(v - hf);
    uint32_t off = swz((uint32_t)(row * 128 + k * 2));
    *reinterpret_cast<__nv_bfloat16*>(hi + off) = h;
    *reinterpret_cast<__nv_bfloat16*>(lo + off) = l;
}

// load one b32 (2 bf16, k-contiguous) from a swizzled 128B-stride tile
DI uint32_t ldt(const char* base, int row, int col) {
    return *reinterpret_cast<const uint32_t*>(base + swz((uint32_t)(row * 128 + col * 2)));
}

// pack two floats -> bf16x2 {lo=e, hi=o}
DI uint32_t packbf(float e, float o) {
    __nv_bfloat162 p;
    p.x = __float2bfloat16(e);
    p.y = __float2bfloat16(o);
    return *reinterpret_cast<uint32_t*>(&p);
}
DI float bflo(uint32_t u) { return __bfloat162float(reinterpret_cast<__nv_bfloat162*>(&u)->x); }
DI float bfhi(uint32_t u) { return __bfloat162float(reinterpret_cast<__nv_bfloat162*>(&u)->y); }

// D[16x8] += A[16x16] * B[16x8]  (bf16 in, f32 acc)  -- sm_80 baseline HMMA
DI void mma16816(float* c, uint32_t a0, uint32_t a1, uint32_t a2, uint32_t a3,
                 uint32_t b0, uint32_t b1) {
    asm volatile(
        "mma.sync.aligned.m16n8k16.row.col.f32.bf16.bf16.f32 "
        "{%0,%1,%2,%3}, {%4,%5,%6,%7}, {%8,%9}, {%0,%1,%2,%3};"
        : "+f"(c[0]), "+f"(c[1]), "+f"(c[2]), "+f"(c[3])
        : "r"(a0), "r"(a1), "r"(a2), "r"(a3), "r"(b0), "r"(b1));
}

__global__ void __launch_bounds__(128)
atomic_mlp_kernel(const float* __restrict__ desc, const int* __restrict__ numbers,
                  const float* __restrict__ W1, const float* __restrict__ b1,
                  const float* __restrict__ W2, const float* __restrict__ b2,
                  const float* __restrict__ W3, const float* __restrict__ b3,
                  float* __restrict__ out) {
    extern __shared__ char smem[];
    const int tid = threadIdx.x, wid = tid >> 5, lid = tid & 31;
    const int g = lid >> 2, t = lid & 3;          // mma quad coords
    const int a = blockIdx.x, nb = blockIdx.y;

    const int s = __ldg(numbers + a);
    const float* W1s = W1 + (size_t)s * DIN * HID;
    const float* b1s = b1 + s * HID;
    const float* W2s = W2 + (size_t)s * HID * HID;
    const float* b2s = b2 + s * HID;
    const float* W3s = W3 + s * HID;
    const float  b3v = __ldg(b3 + s);

    // ---- stage W3 (zero-padded to 64) ----
    if (tid < 64)
        reinterpret_cast<float*>(smem + SM_W3)[tid] = (tid < HID) ? __ldg(W3s + tid) : 0.0f;

    // ---- stage X tile: 128 rows x (39 feats | bias 1.0 at col 39 | zeros to 63) ----
    {
        char* AH = smem + SM_AH; char* AL = smem + SM_AL;
        #pragma unroll 4
        for (int r = 0; r < 32; r++) {
            int row = wid * 32 + r;
            size_t n = (size_t)nb * 128 + row;
            const float* src = desc + (n * A_ATOMS + a) * DIN;
            float v0 = __ldg(src + lid);                           // lid < 39 always
            int k2 = lid + 32;
            float v1 = (k2 < DIN) ? __ldg(src + k2) : (k2 == DIN ? 1.0f : 0.0f);
            st_split(AH, AL, row, lid, v0);
            st_split(AH, AL, row, k2, v1);
        }
    }
    // ---- stage B1[n][k] = W1[k][n], k==39 -> b1[n], zero-pad; 64x64 ----
    {
        char* BH = smem + SM_B1H; char* BL = smem + SM_B1L;
        #pragma unroll 4
        for (int idx = tid; idx < 64 * 64; idx += 128) {
            int n = idx >> 6, k = idx & 63;
            float v = 0.0f;
            if (n < HID) {
                if (k < DIN)       v = __ldg(W1s + k * HID + n);
                else if (k == DIN) v = __ldg(b1s + n);
            }
            st_split(BH, BL, n, k, v);
        }
    }
    // ---- stage B2[n][k] = W2[k][n], k==50 -> b2[n], zero-pad; 64x64 ----
    {
        char* BH = smem + SM_B2H; char* BL = smem + SM_B2L;
        #pragma unroll 4
        for (int idx = tid; idx < 64 * 64; idx += 128) {
            int n = idx >> 6, k = idx & 63;
            float v = 0.0f;
            if (n < HID) {
                if (k < HID)       v = __ldg(W2s + k * HID + n);
                else if (k == HID) v = __ldg(b2s + n);
            }
            st_split(BH, BL, n, k, v);
        }
    }
    __syncthreads();   // last sync: everything below is warp-independent

    const int warp_m = wid * 32;
    const char* AH = smem + SM_AH;  const char* AL = smem + SM_AL;
    const char* B1H = smem + SM_B1H; const char* B1L = smem + SM_B1L;
    const char* B2H = smem + SM_B2H; const char* B2L = smem + SM_B2L;

    // ================= layer 1: D1[128x64] = X[128x48] * B1^T =================
    float acc[2][8][4];
    #pragma unroll
    for (int m = 0; m < 2; m++)
        #pragma unroll
        for (int j = 0; j < 8; j++)
            #pragma unroll
            for (int q = 0; q < 4; q++) acc[m][j][q] = 0.0f;

    #pragma unroll
    for (int ks = 0; ks < 3; ks++) {
        int kc = 16 * ks + 2 * t;
        uint32_t ah[2][4], al[2][4];
        #pragma unroll
        for (int m = 0; m < 2; m++) {
            int r0 = warp_m + m * 16 + g;
            ah[m][0] = ldt(AH, r0,     kc);     al[m][0] = ldt(AL, r0,     kc);
            ah[m][1] = ldt(AH, r0 + 8, kc);     al[m][1] = ldt(AL, r0 + 8, kc);
            ah[m][2] = ldt(AH, r0,     kc + 8); al[m][2] = ldt(AL, r0,     kc + 8);
            ah[m][3] = ldt(AH, r0 + 8, kc + 8); al[m][3] = ldt(AL, r0 + 8, kc + 8);
        }
        #pragma unroll
        for (int j = 0; j < 8; j++) {
            int rn = j * 8 + g;
            uint32_t bh0 = ldt(B1H, rn, kc),     bh1 = ldt(B1H, rn, kc + 8);
            uint32_t bl0 = ldt(B1L, rn, kc),     bl1 = ldt(B1L, rn, kc + 8);
            #pragma unroll
            for (int m = 0; m < 2; m++) {
                mma16816(acc[m][j], ah[m][0], ah[m][1], ah[m][2], ah[m][3], bh0, bh1);
                mma16816(acc[m][j], al[m][0], al[m][1], al[m][2], al[m][3], bh0, bh1);
                mma16816(acc[m][j], ah[m][0], ah[m][1], ah[m][2], ah[m][3], bl0, bl1);
            }
        }
    }

    // ======= silu + bf16 split + repack acc -> layer-2 A fragments (in regs) =======
    // acc n-tile pair (2ks, 2ks+1) is exactly the A fragment for kstep ks.
    uint32_t A2h[2][4][4], A2l[2][4][4];
    #pragma unroll
    for (int m = 0; m < 2; m++)
        #pragma unroll
        for (int ks = 0; ks < 4; ks++) {
            const float* p0 = acc[m][2 * ks];
            const float* p1 = acc[m][2 * ks + 1];
            float v[8] = { fsilu(p0[0]), fsilu(p0[1]), fsilu(p0[2]), fsilu(p0[3]),
                           fsilu(p1[0]), fsilu(p1[1]), fsilu(p1[2]), fsilu(p1[3]) };
            if (ks == 3 && t == 1) {   // cols {50,51}: bias column -> {1, 0}
                v[0] = 1.0f; v[1] = 0.0f;   // row g
                v[2] = 1.0f; v[3] = 0.0f;   // row g+8
            }
            #pragma unroll
            for (int q = 0; q < 4; q++) {
                float e = v[2 * q], o = v[2 * q + 1];
                uint32_t h = packbf(e, o);
                A2h[m][ks][q] = h;
                A2l[m][ks][q] = packbf(e - bflo(h), o - bfhi(h));
            }
        }

    // ================= layer 2: D2[128x64] = H[128x52] * B2^T =================
    float acc2[2][8][4];
    #pragma unroll
    for (int m = 0; m < 2; m++)
        #pragma unroll
        for (int j = 0; j < 8; j++)
            #pragma unroll
            for (int q = 0; q < 4; q++) acc2[m][j][q] = 0.0f;

    #pragma unroll
    for (int ks = 0; ks < 4; ks++) {
        int kc = 16 * ks + 2 * t;
        #pragma unroll
        for (int j = 0; j < 8; j++) {
            int rn = j * 8 + g;
            uint32_t bh0 = ldt(B2H, rn, kc),     bh1 = ldt(B2H, rn, kc + 8);
            uint32_t bl0 = ldt(B2L, rn, kc),     bl1 = ldt(B2L, rn, kc + 8);
            #pragma unroll
            for (int m = 0; m < 2; m++) {
                uint32_t* ah = A2h[m][ks];
                uint32_t* al = A2l[m][ks];
                mma16816(acc2[m][j], ah[0], ah[1], ah[2], ah[3], bh0, bh1);
                mma16816(acc2[m][j], al[0], al[1], al[2], al[3], bh0, bh1);
                mma16816(acc2[m][j], ah[0], ah[1], ah[2], ah[3], bl0, bl1);
            }
        }
    }

    // ========= layer 3: out = silu(D2[:, :50]) . w3 + b3  (w3 zero-padded) =========
    const float* w3s = reinterpret_cast<const float*>(smem + SM_W3);
    #pragma unroll
    for (int m = 0; m < 2; m++) {
        float p0 = 0.0f, p1 = 0.0f;
        #pragma unroll
        for (int j = 0; j < 8; j++) {
            int c0 = 8 * j + 2 * t;
            float w0 = w3s[c0], w1 = w3s[c0 + 1];
            p0 = fmaf(fsilu(acc2[m][j][0]), w0, p0);
            p0 = fmaf(fsilu(acc2[m][j][1]), w1, p0);
            p1 = fmaf(fsilu(acc2[m][j][2]), w0, p1);
            p1 = fmaf(fsilu(acc2[m][j][3]), w1, p1);
        }
        p0 += __shfl_xor_sync(0xffffffffu, p0, 1);
        p0 += __shfl_xor_sync(0xffffffffu, p0, 2);
        p1 += __shfl_xor_sync(0xffffffffu, p1, 1);
        p1 += __shfl_xor_sync(0xffffffffu, p1, 2);
        if (t == 0) {
            size_t n0 = (size_t)nb * 128 + warp_m + m * 16 + g;
            out[n0 * A_ATOMS + a]       = p0 + b3v;
            out[(n0 + 8) * A_ATOMS + a] = p1 + b3v;
        }
    }
}

extern "C" void kernel_launch(void* const* d_in, const int* in_sizes, int n_in,
                              void* d_out, int out_size) {
    const float* desc    = (const float*)d_in[0];
    const int*   numbers = (const int*)  d_in[1];
    const float* W1      = (const float*)d_in[2];
    const float* b1      = (const float*)d_in[3];
    const float* W2      = (const float*)d_in[4];
    const float* b2      = (const float*)d_in[5];
    const float* W3      = (const float*)d_in[6];
    const float* b3      = (const float*)d_in[7];
    float* out           = (float*)d_out;

    cudaFuncSetAttribute(atomic_mlp_kernel,
                         cudaFuncAttributeMaxDynamicSharedMemorySize, SM_TOTAL);
    dim3 grid(A_ATOMS, 32);   // 256 atoms x 32 row-blocks of 128 samples
    atomic_mlp_kernel<<<grid, 128, SM_TOTAL>>>(desc, numbers, W1, b1, W2, b2,
                                               W3, b3, out);
}

// round 6
// speedup vs baseline: 1.0002x; 1.0002x over previous
#include <cuda_runtime.h>
#include <cuda_bf16.h>
#include <cstdint>
#include <cstddef>

#define DI __device__ __forceinline__

static constexpr int A_ATOMS = 256;
static constexpr int DIN     = 39;   // input features; col 39 = bias (1.0)
static constexpr int HID     = 50;   // hidden; layer-2 bias at col 50

// ---- dynamic smem layout (tiles are 128B-stride SW128-swizzled) ----
static constexpr int SM_W3   = 0;                   // 64 floats (zero-padded)
static constexpr int SM_B3   = 64 * 4;              // 1 float
static constexpr int SM_AH   = 1024;                // 128 rows x 128B  (X hi)
static constexpr int SM_AL   = SM_AH  + 16384;      // X lo
static constexpr int SM_B1H  = SM_AL  + 16384;      // 64 rows x 128B
static constexpr int SM_B1L  = SM_B1H + 8192;
static constexpr int SM_B2H  = SM_B1L + 8192;
static constexpr int SM_B2L  = SM_B2H + 8192;
static constexpr int SM_TOTAL = SM_B2L + 8192;      // 66560 B -> ~3 CTAs/SM

DI uint32_t swz(uint32_t off) { return off ^ ((off >> 3) & 0x70); }

DI float fsilu(float x) {
    float e, r;
    asm("ex2.approx.f32 %0, %1;" : "=f"(e) : "f"(x * -1.4426950408889634f));
    asm("rcp.approx.f32 %0, %1;" : "=f"(r) : "f"(e + 1.0f));
    return x * r;   // x * sigmoid(x)
}

// split v into bf16 hi + bf16 lo, store into two swizzled tiles at (row, col)
DI void st_split(char* hi, char* lo, int row, int k, float v) {
    __nv_bfloat16 h = __float2bfloat16(v);
    float hf = __bfloat162float(h);
    __nv_bfloat16 l = __float2bfloat16(v - hf);
    uint32_t off = swz((uint32_t)(row * 128 + k * 2));
    *reinterpret_cast<__nv_bfloat16*>(hi + off) = h;
    *reinterpret_cast<__nv_bfloat16*>(lo + off) = l;
}

// load one b32 (2 bf16, k-contiguous) from a swizzled 128B-stride tile
DI uint32_t ldt(const char* base, int row, int col) {
    return *reinterpret_cast<const uint32_t*>(base + swz((uint32_t)(row * 128 + col * 2)));
}

// pack two floats -> bf16x2 {lo=e, hi=o}
DI uint32_t packbf(float e, float o) {
    __nv_bfloat162 p;
    p.x = __float2bfloat16(e);
    p.y = __float2bfloat16(o);
    return *reinterpret_cast<uint32_t*>(&p);
}
DI float bflo(uint32_t u) { return __bfloat162float(reinterpret_cast<__nv_bfloat162*>(&u)->x); }
DI float bfhi(uint32_t u) { return __bfloat162float(reinterpret_cast<__nv_bfloat162*>(&u)->y); }

// D[16x8] += A[16x16] * B[16x8]  (bf16 in, f32 acc)  -- sm_80 baseline HMMA
DI void mma16816(float* c, uint32_t a0, uint32_t a1, uint32_t a2, uint32_t a3,
                 uint32_t b0, uint32_t b1) {
    asm volatile(
        "mma.sync.aligned.m16n8k16.row.col.f32.bf16.bf16.f32 "
        "{%0,%1,%2,%3}, {%4,%5,%6,%7}, {%8,%9}, {%0,%1,%2,%3};"
        : "+f"(c[0]), "+f"(c[1]), "+f"(c[2]), "+f"(c[3])
        : "r"(a0), "r"(a1), "r"(a2), "r"(a3), "r"(b0), "r"(b1));
}

__global__ void __launch_bounds__(128)
atomic_mlp_kernel(const float* __restrict__ desc, const int* __restrict__ numbers,
                  const float* __restrict__ W1, const float* __restrict__ b1,
                  const float* __restrict__ W2, const float* __restrict__ b2,
                  const float* __restrict__ W3, const float* __restrict__ b3,
                  float* __restrict__ out) {
    extern __shared__ char smem[];
    const int tid = threadIdx.x, wid = tid >> 5, lid = tid & 31;
    const int g = lid >> 2, t = lid & 3;          // mma quad coords
    const int a = blockIdx.x, nb = blockIdx.y;

    const int s = __ldg(numbers + a);
    const float* W1s = W1 + (size_t)s * DIN * HID;
    const float* b1s = b1 + s * HID;
    const float* W2s = W2 + (size_t)s * HID * HID;
    const float* b2s = b2 + s * HID;
    const float* W3s = W3 + s * HID;
    const float  b3v = __ldg(b3 + s);

    // ---- stage W3 (zero-padded to 64) ----
    if (tid < 64)
        reinterpret_cast<float*>(smem + SM_W3)[tid] = (tid < HID) ? __ldg(W3s + tid) : 0.0f;

    // ---- stage X tile: 128 rows x (39 feats | bias 1.0 at col 39 | zeros to 63) ----
    {
        char* AH = smem + SM_AH; char* AL = smem + SM_AL;
        #pragma unroll 4
        for (int r = 0; r < 32; r++) {
            int row = wid * 32 + r;
            size_t n = (size_t)nb * 128 + row;
            const float* src = desc + (n * A_ATOMS + a) * DIN;
            float v0 = __ldg(src + lid);                           // lid < 39 always
            int k2 = lid + 32;
            float v1 = (k2 < DIN) ? __ldg(src + k2) : (k2 == DIN ? 1.0f : 0.0f);
            st_split(AH, AL, row, lid, v0);
            st_split(AH, AL, row, k2, v1);
        }
    }
    // ---- stage B1[n][k] = W1[k][n], k==39 -> b1[n], zero-pad; 64x64 ----
    {
        char* BH = smem + SM_B1H; char* BL = smem + SM_B1L;
        #pragma unroll 4
        for (int idx = tid; idx < 64 * 64; idx += 128) {
            int n = idx >> 6, k = idx & 63;
            float v = 0.0f;
            if (n < HID) {
                if (k < DIN)       v = __ldg(W1s + k * HID + n);
                else if (k == DIN) v = __ldg(b1s + n);
            }
            st_split(BH, BL, n, k, v);
        }
    }
    // ---- stage B2[n][k] = W2[k][n], k==50 -> b2[n], zero-pad; 64x64 ----
    {
        char* BH = smem + SM_B2H; char* BL = smem + SM_B2L;
        #pragma unroll 4
        for (int idx = tid; idx < 64 * 64; idx += 128) {
            int n = idx >> 6, k = idx & 63;
            float v = 0.0f;
            if (n < HID) {
                if (k < HID)       v = __ldg(W2s + k * HID + n);
                else if (k == HID) v = __ldg(b2s + n);
            }
            st_split(BH, BL, n, k, v);
        }
    }
    __syncthreads();   // last sync: everything below is warp-independent

    const int warp_m = wid * 32;
    const char* AH = smem + SM_AH;  const char* AL = smem + SM_AL;
    const char* B1H = smem + SM_B1H; const char* B1L = smem + SM_B1L;
    const char* B2H = smem + SM_B2H; const char* B2L = smem + SM_B2L;

    // ================= layer 1: D1[128x64] = X[128x48] * B1^T =================
    float acc[2][8][4];
    #pragma unroll
    for (int m = 0; m < 2; m++)
        #pragma unroll
        for (int j = 0; j < 8; j++)
            #pragma unroll
            for (int q = 0; q < 4; q++) acc[m][j][q] = 0.0f;

    #pragma unroll
    for (int ks = 0; ks < 3; ks++) {
        int kc = 16 * ks + 2 * t;
        uint32_t ah[2][4], al[2][4];
        #pragma unroll
        for (int m = 0; m < 2; m++) {
            int r0 = warp_m + m * 16 + g;
            ah[m][0] = ldt(AH, r0,     kc);     al[m][0] = ldt(AL, r0,     kc);
            ah[m][1] = ldt(AH, r0 + 8, kc);     al[m][1] = ldt(AL, r0 + 8, kc);
            ah[m][2] = ldt(AH, r0,     kc + 8); al[m][2] = ldt(AL, r0,     kc + 8);
            ah[m][3] = ldt(AH, r0 + 8, kc + 8); al[m][3] = ldt(AL, r0 + 8, kc + 8);
        }
        #pragma unroll
        for (int j = 0; j < 8; j++) {
            int rn = j * 8 + g;
            uint32_t bh0 = ldt(B1H, rn, kc),     bh1 = ldt(B1H, rn, kc + 8);
            uint32_t bl0 = ldt(B1L, rn, kc),     bl1 = ldt(B1L, rn, kc + 8);
            #pragma unroll
            for (int m = 0; m < 2; m++) {
                mma16816(acc[m][j], ah[m][0], ah[m][1], ah[m][2], ah[m][3], bh0, bh1);
                mma16816(acc[m][j], al[m][0], al[m][1], al[m][2], al[m][3], bh0, bh1);
                mma16816(acc[m][j], ah[m][0], ah[m][1], ah[m][2], ah[m][3], bl0, bl1);
            }
        }
    }

    // ======= silu + bf16 split + repack acc -> layer-2 A fragments (in regs) =======
    // acc n-tile pair (2ks, 2ks+1) is exactly the A fragment for kstep ks.
    uint32_t A2h[2][4][4], A2l[2][4][4];
    #pragma unroll
    for (int m = 0; m < 2; m++)
        #pragma unroll
        for (int ks = 0; ks < 4; ks++) {
            const float* p0 = acc[m][2 * ks];
            const float* p1 = acc[m][2 * ks + 1];
            float v[8] = { fsilu(p0[0]), fsilu(p0[1]), fsilu(p0[2]), fsilu(p0[3]),
                           fsilu(p1[0]), fsilu(p1[1]), fsilu(p1[2]), fsilu(p1[3]) };
            if (ks == 3 && t == 1) {   // cols {50,51}: bias column -> {1, 0}
                v[0] = 1.0f; v[1] = 0.0f;   // row g
                v[2] = 1.0f; v[3] = 0.0f;   // row g+8
            }
            #pragma unroll
            for (int q = 0; q < 4; q++) {
                float e = v[2 * q], o = v[2 * q + 1];
                uint32_t h = packbf(e, o);
                A2h[m][ks][q] = h;
                A2l[m][ks][q] = packbf(e - bflo(h), o - bfhi(h));
            }
        }

    // ================= layer 2: D2[128x64] = H[128x52] * B2^T =================
    float acc2[2][8][4];
    #pragma unroll
    for (int m = 0; m < 2; m++)
        #pragma unroll
        for (int j = 0; j < 8; j++)
            #pragma unroll
            for (int q = 0; q < 4; q++) acc2[m][j][q] = 0.0f;

    #pragma unroll
    for (int ks = 0; ks < 4; ks++) {
        int kc = 16 * ks + 2 * t;
        #pragma unroll
        for (int j = 0; j < 8; j++) {
            int rn = j * 8 + g;
            uint32_t bh0 = ldt(B2H, rn, kc),     bh1 = ldt(B2H, rn, kc + 8);
            uint32_t bl0 = ldt(B2L, rn, kc),     bl1 = ldt(B2L, rn, kc + 8);
            #pragma unroll
            for (int m = 0; m < 2; m++) {
                uint32_t* ah = A2h[m][ks];
                uint32_t* al = A2l[m][ks];
                mma16816(acc2[m][j], ah[0], ah[1], ah[2], ah[3], bh0, bh1);
                mma16816(acc2[m][j], al[0], al[1], al[2], al[3], bh0, bh1);
                mma16816(acc2[m][j], ah[0], ah[1], ah[2], ah[3], bl0, bl1);
            }
        }
    }

    // ========= layer 3: out = silu(D2[:, :50]) . w3 + b3  (w3 zero-padded) =========
    const float* w3s = reinterpret_cast<const float*>(smem + SM_W3);
    #pragma unroll
    for (int m = 0; m < 2; m++) {
        float p0 = 0.0f, p1 = 0.0f;
        #pragma unroll
        for (int j = 0; j < 8; j++) {
            int c0 = 8 * j + 2 * t;
            float w0 = w3s[c0], w1 = w3s[c0 + 1];
            p0 = fmaf(fsilu(acc2[m][j][0]), w0, p0);
            p0 = fmaf(fsilu(acc2[m][j][1]), w1, p0);
            p1 = fmaf(fsilu(acc2[m][j][2]), w0, p1);
            p1 = fmaf(fsilu(acc2[m][j][3]), w1, p1);
        }
        p0 += __shfl_xor_sync(0xffffffffu, p0, 1);
        p0 += __shfl_xor_sync(0xffffffffu, p0, 2);
        p1 += __shfl_xor_sync(0xffffffffu, p1, 1);
        p1 += __shfl_xor_sync(0xffffffffu, p1, 2);
        if (t == 0) {
            size_t n0 = (size_t)nb * 128 + warp_m + m * 16 + g;
            out[n0 * A_ATOMS + a]       = p0 + b3v;
            out[(n0 + 8) * A_ATOMS + a] = p1 + b3v;
        }
    }
}

extern "C" void kernel_launch(void* const* d_in, const int* in_sizes, int n_in,
                              void* d_out, int out_size) {
    const float* desc    = (const float*)d_in[0];
    const int*   numbers = (const int*)  d_in[1];
    const float* W1      = (const float*)d_in[2];
    const float* b1      = (const float*)d_in[3];
    const float* W2      = (const float*)d_in[4];
    const float* b2      = (const float*)d_in[5];
    const float* W3      = (const float*)d_in[6];
    const float* b3      = (const float*)d_in[7];
    float* out           = (float*)d_out;

    cudaFuncSetAttribute(atomic_mlp_kernel,
                         cudaFuncAttributeMaxDynamicSharedMemorySize, SM_TOTAL);
    dim3 grid(A_ATOMS, 32);   // 256 atoms x 32 row-blocks of 128 samples
    atomic_mlp_kernel<<<grid, 128, SM_TOTAL>>>(desc, numbers, W1, b1, W2, b2,
                                               W3, b3, out);
}

// round 7
// speedup vs baseline: 1.5304x; 1.5301x over previous
#include <cuda_runtime.h>
#include <cuda_bf16.h>
#include <cstdint>
#include <cstddef>

#define DI __device__ __forceinline__

static constexpr int A_ATOMS = 256;
static constexpr int DIN     = 39;   // input features; col 39 = bias (1.0)
static constexpr int HID     = 50;   // hidden; layer-2 bias at col 50

// ---- dynamic smem layout (tiles 128B-stride, SW128-swizzled) ----
static constexpr int SM_W3   = 0;                   // 64 floats (zero-padded)
static constexpr int SM_AH   = 1024;                // 128 rows x 128B (X hi)
static constexpr int SM_AL   = SM_AH  + 16384;      // X lo
static constexpr int SM_B1H  = SM_AL  + 16384;      // 64 rows x 128B
static constexpr int SM_B1L  = SM_B1H + 8192;
static constexpr int SM_B2H  = SM_B1L + 8192;
static constexpr int SM_B2L  = SM_B2H + 8192;
static constexpr int SM_TOTAL = SM_B2L + 8192;      // 66560 B -> 3 CTAs/SM

DI uint32_t s2u(const void* p) {
    uint32_t a;
    asm("{ .reg .u64 t; cvta.to.shared.u64 t, %1; cvt.u32.u64 %0, t; }"
        : "=r"(a) : "l"(p));
    return a;
}
DI uint32_t swz(uint32_t off) { return off ^ ((off >> 3) & 0x70); }

DI float fsilu(float x) {
    float e, r;
    asm("ex2.approx.f32 %0, %1;" : "=f"(e) : "f"(x * -1.4426950408889634f));
    asm("rcp.approx.f32 %0, %1;" : "=f"(r) : "f"(e + 1.0f));
    return x * r;   // x * sigmoid(x)
}

// split v into bf16 hi + lo, store into two swizzled tiles at (row, col)
DI void st_split(char* hi, char* lo, int row, int k, float v) {
    __nv_bfloat16 h = __float2bfloat16(v);
    float hf = __bfloat162float(h);
    __nv_bfloat16 l = __float2bfloat16(v - hf);
    uint32_t off = swz((uint32_t)(row * 128 + k * 2));
    *reinterpret_cast<__nv_bfloat16*>(hi + off) = h;
    *reinterpret_cast<__nv_bfloat16*>(lo + off) = l;
}

// pack {lo=e, hi=o} floats -> bf16x2
DI uint32_t packbf(float e, float o) {
    uint32_t r;
    asm("cvt.rn.bf16x2.f32 %0, %1, %2;" : "=r"(r) : "f"(o), "f"(e));
    return r;
}
DI float bflo(uint32_t u) {
    __nv_bfloat162 p = *reinterpret_cast<__nv_bfloat162*>(&u);
    return __bfloat162float(p.x);
}
DI float bfhi(uint32_t u) {
    __nv_bfloat162 p = *reinterpret_cast<__nv_bfloat162*>(&u);
    return __bfloat162float(p.y);
}

// D[16x8] += A[16x16]*B[16x8] (bf16 in, f32 acc) -- sm_80 baseline HMMA
DI void mma16816(float* c, const uint32_t* a, uint32_t b0, uint32_t b1) {
    asm volatile(
        "mma.sync.aligned.m16n8k16.row.col.f32.bf16.bf16.f32 "
        "{%0,%1,%2,%3}, {%4,%5,%6,%7}, {%8,%9}, {%0,%1,%2,%3};"
        : "+f"(c[0]), "+f"(c[1]), "+f"(c[2]), "+f"(c[3])
        : "r"(a[0]), "r"(a[1]), "r"(a[2]), "r"(a[3]), "r"(b0), "r"(b1));
}

// ldmatrix x4 (sm_75 baseline): M0,M1,M2,M3 -> r[0..3]
DI void ldm4(uint32_t* r, uint32_t addr) {
    asm volatile("ldmatrix.sync.aligned.m8n8.x4.shared.b16 {%0,%1,%2,%3}, [%4];"
                 : "=r"(r[0]), "=r"(r[1]), "=r"(r[2]), "=r"(r[3]) : "r"(addr));
}

__global__ void __launch_bounds__(256, 3)
atomic_mlp_kernel(const float* __restrict__ desc, const int* __restrict__ numbers,
                  const float* __restrict__ W1, const float* __restrict__ b1,
                  const float* __restrict__ W2, const float* __restrict__ b2,
                  const float* __restrict__ W3, const float* __restrict__ b3,
                  float* __restrict__ out) {
    extern __shared__ char smem[];
    const int tid = threadIdx.x, wid = tid >> 5, lid = tid & 31;
    const int g = lid >> 2, t = lid & 3;          // mma quad coords
    const int a = blockIdx.x, nb = blockIdx.y;
    const int warp_m = wid * 16;                  // each warp owns 16 rows

    const int s = __ldg(numbers + a);
    const float* W1s = W1 + (size_t)s * DIN * HID;
    const float* b1s = b1 + s * HID;
    const float* W2s = W2 + (size_t)s * HID * HID;
    const float* b2s = b2 + s * HID;
    const float* W3s = W3 + s * HID;
    const float  b3v = __ldg(b3 + s);

    // ---- stage W3 (zero-padded to 64) ----
    if (tid < 64)
        reinterpret_cast<float*>(smem + SM_W3)[tid] = (tid < HID) ? __ldg(W3s + tid) : 0.0f;

    // ---- stage X: warp stages its own 16 rows (39 feats | 1.0 at 39 | zeros) ----
    {
        char* AH = smem + SM_AH; char* AL = smem + SM_AL;
        #pragma unroll 4
        for (int r = 0; r < 16; r++) {
            int row = warp_m + r;
            size_t n = (size_t)nb * 128 + row;
            const float* src = desc + (n * A_ATOMS + a) * DIN;
            float v0 = __ldg(src + lid);                           // lid < 39 always
            int k2 = lid + 32;
            float v1 = (k2 < DIN) ? __ldg(src + k2) : (k2 == DIN ? 1.0f : 0.0f);
            st_split(AH, AL, row, lid, v0);
            st_split(AH, AL, row, k2, v1);
        }
    }
    // ---- stage B1[n][k] = W1[k][n], k==39 -> b1[n], zero-pad; 64x64 ----
    {
        char* BH = smem + SM_B1H; char* BL = smem + SM_B1L;
        #pragma unroll 4
        for (int idx = tid; idx < 64 * 64; idx += 256) {
            int n = idx >> 6, k = idx & 63;
            float v = 0.0f;
            if (n < HID) {
                if (k < DIN)       v = __ldg(W1s + k * HID + n);
                else if (k == DIN) v = __ldg(b1s + n);
            }
            st_split(BH, BL, n, k, v);
        }
    }
    // ---- stage B2[n][k] = W2[k][n], k==50 -> b2[n], zero-pad; 64x64 ----
    {
        char* BH = smem + SM_B2H; char* BL = smem + SM_B2L;
        #pragma unroll 4
        for (int idx = tid; idx < 64 * 64; idx += 256) {
            int n = idx >> 6, k = idx & 63;
            float v = 0.0f;
            if (n < HID) {
                if (k < HID)       v = __ldg(W2s + k * HID + n);
                else if (k == HID) v = __ldg(b2s + n);
            }
            st_split(BH, BL, n, k, v);
        }
    }
    __syncthreads();   // only CTA-wide sync

    // ---- ldmatrix per-lane addressing (closed-form swizzle) ----
    const uint32_t sb = s2u(smem);
    const int lr = lid & 15, cb = lid >> 4, s7 = lr & 7;
    const uint32_t aAH = sb + SM_AH + (uint32_t)(warp_m + lr) * 128;
    const uint32_t aAL = sb + SM_AL + (uint32_t)(warp_m + lr) * 128;
    const uint32_t rB  = (uint32_t)lr * 128;

    // X hi fragments resident (3 ksteps)
    uint32_t Xh[3][4];
    #pragma unroll
    for (int ks = 0; ks < 3; ks++)
        ldm4(Xh[ks], aAH + ((((uint32_t)(2 * ks + cb)) ^ s7) << 4));

    uint32_t A2h[4][4], A2l[4][4];

    // ================= layer 1 (j-pair outer), repack into A2 =================
    #pragma unroll
    for (int jp = 0; jp < 4; jp++) {
        float acc0[4] = {0, 0, 0, 0}, acc1[4] = {0, 0, 0, 0};
        const uint32_t bH = sb + SM_B1H + (uint32_t)jp * 2048 + rB;
        const uint32_t bL = sb + SM_B1L + (uint32_t)jp * 2048 + rB;
        #pragma unroll
        for (int ks = 0; ks < 3; ks++) {
            uint32_t off = (((uint32_t)(2 * ks + cb)) ^ s7) << 4;
            uint32_t bh[4], bl[4], xl[4];
            ldm4(bh, bH + off);
            ldm4(bl, bL + off);
            ldm4(xl, aAL + off);
            mma16816(acc0, Xh[ks], bh[0], bh[2]);
            mma16816(acc0, xl,     bh[0], bh[2]);
            mma16816(acc0, Xh[ks], bl[0], bl[2]);
            if (jp < 3) {                              // j=7 (cols 56-63) dead
                mma16816(acc1, Xh[ks], bh[1], bh[3]);
                mma16816(acc1, xl,     bh[1], bh[3]);
                mma16816(acc1, Xh[ks], bl[1], bl[3]);
            }
        }
        // silu + bf16 split -> A2 fragment kstep jp (slots 0,1 = even j)
        float v0 = fsilu(acc0[0]), v1 = fsilu(acc0[1]);
        float v2 = fsilu(acc0[2]), v3 = fsilu(acc0[3]);
        if (jp == 3 && t == 1) { v0 = 1.0f; v1 = 0.0f; v2 = 1.0f; v3 = 0.0f; } // bias col 50
        uint32_t h0 = packbf(v0, v1), h1 = packbf(v2, v3);
        A2h[jp][0] = h0; A2l[jp][0] = packbf(v0 - bflo(h0), v1 - bfhi(h0));
        A2h[jp][1] = h1; A2l[jp][1] = packbf(v2 - bflo(h1), v3 - bfhi(h1));
        if (jp < 3) {                                  // slots 2,3 = odd j
            float u0 = fsilu(acc1[0]), u1 = fsilu(acc1[1]);
            float u2 = fsilu(acc1[2]), u3 = fsilu(acc1[3]);
            uint32_t h2 = packbf(u0, u1), h3 = packbf(u2, u3);
            A2h[jp][2] = h2; A2l[jp][2] = packbf(u0 - bflo(h2), u1 - bfhi(h2));
            A2h[jp][3] = h3; A2l[jp][3] = packbf(u2 - bflo(h3), u3 - bfhi(h3));
        } else {                                        // cols 56-63 = 0
            A2h[jp][2] = 0; A2h[jp][3] = 0; A2l[jp][2] = 0; A2l[jp][3] = 0;
        }
    }

    // ============ layer 2 (j-pair outer) with fused layer-3 dot ============
    const float* w3s = reinterpret_cast<const float*>(smem + SM_W3);
    float p0 = 0.0f, p1 = 0.0f;
    #pragma unroll
    for (int jp = 0; jp < 4; jp++) {
        float acc0[4] = {0, 0, 0, 0}, acc1[4] = {0, 0, 0, 0};
        const uint32_t bH = sb + SM_B2H + (uint32_t)jp * 2048 + rB;
        const uint32_t bL = sb + SM_B2L + (uint32_t)jp * 2048 + rB;
        #pragma unroll
        for (int ks = 0; ks < 4; ks++) {
            uint32_t off = (((uint32_t)(2 * ks + cb)) ^ s7) << 4;
            uint32_t bh[4], bl[4];
            ldm4(bh, bH + off);
            ldm4(bl, bL + off);
            mma16816(acc0, A2h[ks], bh[0], bh[2]);
            mma16816(acc0, A2l[ks], bh[0], bh[2]);
            mma16816(acc0, A2h[ks], bl[0], bl[2]);
            if (jp < 3) {
                mma16816(acc1, A2h[ks], bh[1], bh[3]);
                mma16816(acc1, A2l[ks], bh[1], bh[3]);
                mma16816(acc1, A2h[ks], bl[1], bl[3]);
            }
        }
        int c0 = 16 * jp + 2 * t;                      // even j cols
        float w0 = w3s[c0], w1 = w3s[c0 + 1];
        p0 = fmaf(fsilu(acc0[0]), w0, p0); p0 = fmaf(fsilu(acc0[1]), w1, p0);
        p1 = fmaf(fsilu(acc0[2]), w0, p1); p1 = fmaf(fsilu(acc0[3]), w1, p1);
        if (jp < 3) {
            int c1 = c0 + 8;                           // odd j cols
            float y0 = w3s[c1], y1 = w3s[c1 + 1];
            p0 = fmaf(fsilu(acc1[0]), y0, p0); p0 = fmaf(fsilu(acc1[1]), y1, p0);
            p1 = fmaf(fsilu(acc1[2]), y0, p1); p1 = fmaf(fsilu(acc1[3]), y1, p1);
        }
    }

    // reduce over t quads and store
    p0 += __shfl_xor_sync(0xffffffffu, p0, 1);
    p0 += __shfl_xor_sync(0xffffffffu, p0, 2);
    p1 += __shfl_xor_sync(0xffffffffu, p1, 1);
    p1 += __shfl_xor_sync(0xffffffffu, p1, 2);
    if (t == 0) {
        size_t n0 = (size_t)nb * 128 + warp_m + g;
        out[n0 * A_ATOMS + a]       = p0 + b3v;
        out[(n0 + 8) * A_ATOMS + a] = p1 + b3v;
    }
}

extern "C" void kernel_launch(void* const* d_in, const int* in_sizes, int n_in,
                              void* d_out, int out_size) {
    const float* desc    = (const float*)d_in[0];
    const int*   numbers = (const int*)  d_in[1];
    const float* W1      = (const float*)d_in[2];
    const float* b1      = (const float*)d_in[3];
    const float* W2      = (const float*)d_in[4];
    const float* b2      = (const float*)d_in[5];
    const float* W3      = (const float*)d_in[6];
    const float* b3      = (const float*)d_in[7];
    float* out           = (float*)d_out;

    cudaFuncSetAttribute(atomic_mlp_kernel,
                         cudaFuncAttributeMaxDynamicSharedMemorySize, SM_TOTAL);
    dim3 grid(A_ATOMS, 32);   // 256 atoms x 32 row-blocks of 128 samples
    atomic_mlp_kernel<<<grid, 256, SM_TOTAL>>>(desc, numbers, W1, b1, W2, b2,
                                               W3, b3, out);
}

// round 9
// speedup vs baseline: 2.3386x; 1.5281x over previous
#include <cuda_runtime.h>
#include <cuda_bf16.h>
#include <cstdint>
#include <cstddef>

#define DI __device__ __forceinline__

static constexpr int A_ATOMS = 256;
static constexpr int DIN     = 39;   // input features; col 39 = bias (1.0)
static constexpr int HID     = 50;   // hidden; layer-2 bias at col 50
static constexpr int NSPEC   = 8;

// per-species precomputed weight tiles: B1H|B1L|B2H|B2L, each 64 rows x 128B,
// SW128-swizzled, exactly the layout the main kernel's ldmatrix expects.
__device__ __align__(16) uint8_t g_wt[NSPEC][4 * 8192];

// ---- dynamic smem layout (tiles 128B-stride, SW128-swizzled) ----
static constexpr int SM_W3   = 0;                   // 64 floats (zero-padded)
static constexpr int SM_AH   = 1024;                // 128 rows x 128B (X hi)
static constexpr int SM_AL   = SM_AH  + 16384;      // X lo
static constexpr int SM_B1H  = SM_AL  + 16384;      // weight block: 4 x 8192 contiguous
static constexpr int SM_B1L  = SM_B1H + 8192;
static constexpr int SM_B2H  = SM_B1L + 8192;
static constexpr int SM_B2L  = SM_B2H + 8192;
static constexpr int SM_TOTAL = SM_B2L + 8192;      // 66560 B -> 3 CTAs/SM

DI uint32_t s2u(const void* p) {
    uint32_t a;
    asm("{ .reg .u64 t; cvta.to.shared.u64 t, %1; cvt.u32.u64 %0, t; }"
        : "=r"(a) : "l"(p));
    return a;
}
DI uint32_t swz(uint32_t off) { return off ^ ((off >> 3) & 0x70); }

DI float fsilu(float x) {
    float e, r;
    asm("ex2.approx.f32 %0, %1;" : "=f"(e) : "f"(x * -1.4426950408889634f));
    asm("rcp.approx.f32 %0, %1;" : "=f"(r) : "f"(e + 1.0f));
    return x * r;   // x * sigmoid(x)
}

// split v into bf16 hi + lo, store into two swizzled tiles at (row, col)
DI void st_split(char* hi, char* lo, int row, int k, float v) {
    __nv_bfloat16 h = __float2bfloat16(v);
    float hf = __bfloat162float(h);
    __nv_bfloat16 l = __float2bfloat16(v - hf);
    uint32_t off = swz((uint32_t)(row * 128 + k * 2));
    *reinterpret_cast<__nv_bfloat16*>(hi + off) = h;
    *reinterpret_cast<__nv_bfloat16*>(lo + off) = l;
}

// pack {lo=e, hi=o} floats -> bf16x2
DI uint32_t packbf(float e, float o) {
    uint32_t r;
    asm("cvt.rn.bf16x2.f32 %0, %1, %2;" : "=r"(r) : "f"(o), "f"(e));
    return r;
}
DI float bflo(uint32_t u) {
    __nv_bfloat162 p = *reinterpret_cast<__nv_bfloat162*>(&u);
    return __bfloat162float(p.x);
}
DI float bfhi(uint32_t u) {
    __nv_bfloat162 p = *reinterpret_cast<__nv_bfloat162*>(&u);
    return __bfloat162float(p.y);
}

// D[16x8] += A[16x16]*B[16x8] (bf16 in, f32 acc) -- sm_80 baseline HMMA
DI void mma16816(float* c, const uint32_t* a, uint32_t b0, uint32_t b1) {
    asm volatile(
        "mma.sync.aligned.m16n8k16.row.col.f32.bf16.bf16.f32 "
        "{%0,%1,%2,%3}, {%4,%5,%6,%7}, {%8,%9}, {%0,%1,%2,%3};"
        : "+f"(c[0]), "+f"(c[1]), "+f"(c[2]), "+f"(c[3])
        : "r"(a[0]), "r"(a[1]), "r"(a[2]), "r"(a[3]), "r"(b0), "r"(b1));
}

// ldmatrix x4 (sm_75 baseline)
DI void ldm4(uint32_t* r, uint32_t addr) {
    asm volatile("ldmatrix.sync.aligned.m8n8.x4.shared.b16 {%0,%1,%2,%3}, [%4];"
                 : "=r"(r[0]), "=r"(r[1]), "=r"(r[2]), "=r"(r[3]) : "r"(addr));
}

// ===================== prologue: build per-species weight tiles =====================
__global__ void __launch_bounds__(256)
prep_weights(const float* __restrict__ W1, const float* __restrict__ b1,
             const float* __restrict__ W2, const float* __restrict__ b2) {
    const int s = blockIdx.x, tid = threadIdx.x;
    char* B1H = reinterpret_cast<char*>(g_wt[s]);
    char* B1L = B1H + 8192;
    char* B2H = B1L + 8192;
    char* B2L = B2H + 8192;
    const float* W1s = W1 + (size_t)s * DIN * HID;
    const float* b1s = b1 + s * HID;
    const float* W2s = W2 + (size_t)s * HID * HID;
    const float* b2s = b2 + s * HID;

    // B1[n][k] = W1[k][n]; k==39 -> b1[n]; zero-pad to 64x64
    for (int idx = tid; idx < 64 * 64; idx += 256) {
        int n = idx >> 6, k = idx & 63;
        float v = 0.0f;
        if (n < HID) {
            if (k < DIN)       v = __ldg(W1s + k * HID + n);
            else if (k == DIN) v = __ldg(b1s + n);
        }
        st_split(B1H, B1L, n, k, v);
    }
    // B2[n][k] = W2[k][n]; k==50 -> b2[n]; zero-pad to 64x64
    for (int idx = tid; idx < 64 * 64; idx += 256) {
        int n = idx >> 6, k = idx & 63;
        float v = 0.0f;
        if (n < HID) {
            if (k < HID)       v = __ldg(W2s + k * HID + n);
            else if (k == HID) v = __ldg(b2s + n);
        }
        st_split(B2H, B2L, n, k, v);
    }
}

// ================================ main kernel ================================
__global__ void __launch_bounds__(256, 3)
atomic_mlp_kernel(const float* __restrict__ desc, const int* __restrict__ numbers,
                  const float* __restrict__ W3, const float* __restrict__ b3,
                  float* __restrict__ out) {
    extern __shared__ char smem[];
    const int tid = threadIdx.x, wid = tid >> 5, lid = tid & 31;
    const int g = lid >> 2, t = lid & 3;          // mma quad coords
    const int a = blockIdx.x, nb = blockIdx.y;
    const int warp_m = wid * 16;                  // each warp owns 16 rows

    const int s = __ldg(numbers + a);
    const float* W3s = W3 + s * HID;
    const float  b3v = __ldg(b3 + s);

    // ---- stage X: warp stages its own 16 rows (39 feats | 1.0 at 39 | zeros) ----
    {
        char* AH = smem + SM_AH; char* AL = smem + SM_AL;
        #pragma unroll 4
        for (int r = 0; r < 16; r++) {
            int row = warp_m + r;
            size_t n = (size_t)nb * 128 + row;
            const float* src = desc + (n * A_ATOMS + a) * DIN;
            float v0 = __ldg(src + lid);                           // lid < 39 always
            int k2 = lid + 32;
            float v1 = (k2 < DIN) ? __ldg(src + k2) : (k2 == DIN ? 1.0f : 0.0f);
            st_split(AH, AL, row, lid, v0);
            st_split(AH, AL, row, k2, v1);
        }
    }
    // ---- stage weights: straight 32KB copy of pre-swizzled tiles (L2-resident) ----
    {
        const uint4* src = reinterpret_cast<const uint4*>(g_wt[s]);
        uint4* dst = reinterpret_cast<uint4*>(smem + SM_B1H);
        #pragma unroll
        for (int i = 0; i < 8; i++)
            dst[tid + 256 * i] = __ldg(src + tid + 256 * i);
    }
    // ---- stage W3 (zero-padded to 64) ----
    if (tid < 64)
        reinterpret_cast<float*>(smem + SM_W3)[tid] = (tid < HID) ? __ldg(W3s + tid) : 0.0f;
    __syncthreads();   // only CTA-wide sync

    // ---- ldmatrix per-lane addressing (closed-form swizzle) ----
    const uint32_t sb = s2u(smem);
    const int lr = lid & 15, cb = lid >> 4, s7 = lr & 7;
    const uint32_t aAH = sb + SM_AH + (uint32_t)(warp_m + lr) * 128;
    const uint32_t aAL = sb + SM_AL + (uint32_t)(warp_m + lr) * 128;
    const uint32_t rB  = (uint32_t)lr * 128;

    // X hi fragments resident (3 ksteps)
    uint32_t Xh[3][4];
    #pragma unroll
    for (int ks = 0; ks < 3; ks++)
        ldm4(Xh[ks], aAH + ((((uint32_t)(2 * ks + cb)) ^ s7) << 4));

    uint32_t A2h[4][4], A2l[4][4];

    // ================= layer 1 (j-pair outer), repack into A2 =================
    #pragma unroll
    for (int jp = 0; jp < 4; jp++) {
        float acc0[4] = {0, 0, 0, 0}, acc1[4] = {0, 0, 0, 0};
        const uint32_t bH = sb + SM_B1H + (uint32_t)jp * 2048 + rB;
        const uint32_t bL = sb + SM_B1L + (uint32_t)jp * 2048 + rB;
        #pragma unroll
        for (int ks = 0; ks < 3; ks++) {
            uint32_t off = (((uint32_t)(2 * ks + cb)) ^ s7) << 4;
            uint32_t bh[4], bl[4], xl[4];
            ldm4(bh, bH + off);
            ldm4(bl, bL + off);
            ldm4(xl, aAL + off);
            mma16816(acc0, Xh[ks], bh[0], bh[2]);
            mma16816(acc0, xl,     bh[0], bh[2]);
            mma16816(acc0, Xh[ks], bl[0], bl[2]);
            if (jp < 3) {                              // j=7 (cols 56-63) dead
                mma16816(acc1, Xh[ks], bh[1], bh[3]);
                mma16816(acc1, xl,     bh[1], bh[3]);
                mma16816(acc1, Xh[ks], bl[1], bl[3]);
            }
        }
        // silu + bf16 split -> A2 fragment kstep jp (slots 0,1 = even j)
        float v0 = fsilu(acc0[0]), v1 = fsilu(acc0[1]);
        float v2 = fsilu(acc0[2]), v3 = fsilu(acc0[3]);
        if (jp == 3 && t == 1) { v0 = 1.0f; v1 = 0.0f; v2 = 1.0f; v3 = 0.0f; } // bias col 50
        uint32_t h0 = packbf(v0, v1), h1 = packbf(v2, v3);
        A2h[jp][0] = h0; A2l[jp][0] = packbf(v0 - bflo(h0), v1 - bfhi(h0));
        A2h[jp][1] = h1; A2l[jp][1] = packbf(v2 - bflo(h1), v3 - bfhi(h1));
        if (jp < 3) {                                  // slots 2,3 = odd j
            float u0 = fsilu(acc1[0]), u1 = fsilu(acc1[1]);
            float u2 = fsilu(acc1[2]), u3 = fsilu(acc1[3]);
            uint32_t h2 = packbf(u0, u1), h3 = packbf(u2, u3);
            A2h[jp][2] = h2; A2l[jp][2] = packbf(u0 - bflo(h2), u1 - bfhi(h2));
            A2h[jp][3] = h3; A2l[jp][3] = packbf(u2 - bflo(h3), u3 - bfhi(h3));
        } else {                                        // cols 56-63 = 0
            A2h[jp][2] = 0; A2h[jp][3] = 0; A2l[jp][2] = 0; A2l[jp][3] = 0;
        }
    }

    // ============ layer 2 (j-pair outer) with fused layer-3 dot ============
    const float* w3s = reinterpret_cast<const float*>(smem + SM_W3);
    float p0 = 0.0f, p1 = 0.0f;
    #pragma unroll
    for (int jp = 0; jp < 4; jp++) {
        float acc0[4] = {0, 0, 0, 0}, acc1[4] = {0, 0, 0, 0};
        const uint32_t bH = sb + SM_B2H + (uint32_t)jp * 2048 + rB;
        const uint32_t bL = sb + SM_B2L + (uint32_t)jp * 2048 + rB;
        #pragma unroll
        for (int ks = 0; ks < 4; ks++) {
            uint32_t off = (((uint32_t)(2 * ks + cb)) ^ s7) << 4;
            uint32_t bh[4], bl[4];
            ldm4(bh, bH + off);
            ldm4(bl, bL + off);
            mma16816(acc0, A2h[ks], bh[0], bh[2]);
            mma16816(acc0, A2l[ks], bh[0], bh[2]);
            mma16816(acc0, A2h[ks], bl[0], bl[2]);
            if (jp < 3) {
                mma16816(acc1, A2h[ks], bh[1], bh[3]);
                mma16816(acc1, A2l[ks], bh[1], bh[3]);
                mma16816(acc1, A2h[ks], bl[1], bl[3]);
            }
        }
        int c0 = 16 * jp + 2 * t;                      // even j cols
        float w0 = w3s[c0], w1 = w3s[c0 + 1];
        p0 = fmaf(fsilu(acc0[0]), w0, p0); p0 = fmaf(fsilu(acc0[1]), w1, p0);
        p1 = fmaf(fsilu(acc0[2]), w0, p1); p1 = fmaf(fsilu(acc0[3]), w1, p1);
        if (jp < 3) {
            int c1 = c0 + 8;                           // odd j cols
            float y0 = w3s[c1], y1 = w3s[c1 + 1];
            p0 = fmaf(fsilu(acc1[0]), y0, p0); p0 = fmaf(fsilu(acc1[1]), y1, p0);
            p1 = fmaf(fsilu(acc1[2]), y0, p1); p1 = fmaf(fsilu(acc1[3]), y1, p1);
        }
    }

    // reduce over t quads and store
    p0 += __shfl_xor_sync(0xffffffffu, p0, 1);
    p0 += __shfl_xor_sync(0xffffffffu, p0, 2);
    p1 += __shfl_xor_sync(0xffffffffu, p1, 1);
    p1 += __shfl_xor_sync(0xffffffffu, p1, 2);
    if (t == 0) {
        size_t n0 = (size_t)nb * 128 + warp_m + g;
        out[n0 * A_ATOMS + a]       = p0 + b3v;
        out[(n0 + 8) * A_ATOMS + a] = p1 + b3v;
    }
}

extern "C" void kernel_launch(void* const* d_in, const int* in_sizes, int n_in,
                              void* d_out, int out_size) {
    const float* desc    = (const float*)d_in[0];
    const int*   numbers = (const int*)  d_in[1];
    const float* W1      = (const float*)d_in[2];
    const float* b1      = (const float*)d_in[3];
    const float* W2      = (const float*)d_in[4];
    const float* b2      = (const float*)d_in[5];
    const float* W3      = (const float*)d_in[6];
    const float* b3      = (const float*)d_in[7];
    float* out           = (float*)d_out;

    prep_weights<<<NSPEC, 256>>>(W1, b1, W2, b2);

    cudaFuncSetAttribute(atomic_mlp_kernel,
                         cudaFuncAttributeMaxDynamicSharedMemorySize, SM_TOTAL);
    dim3 grid(A_ATOMS, 32);   // 256 atoms x 32 row-blocks of 128 samples
    atomic_mlp_kernel<<<grid, 256, SM_TOTAL>>>(desc, numbers, W3, b3, out);
}

// round 10
// speedup vs baseline: 2.3456x; 1.0030x over previous
#include <cuda_runtime.h>
#include <cuda_bf16.h>
#include <cstdint>
#include <cstddef>

#define DI __device__ __forceinline__

static constexpr int A_ATOMS = 256;
static constexpr int DIN     = 39;   // input features; col 39 = bias (1.0)
static constexpr int HID     = 50;   // hidden; layer-2 bias at col 50
static constexpr int NSPEC   = 8;

// per-species precomputed weight tiles: B1H|B1L|B2H|B2L, each 64 rows x 128B,
// SW128-swizzled, exactly the layout the main kernel's ldmatrix expects.
__device__ __align__(16) uint8_t g_wt[NSPEC][4 * 8192];

// ---- dynamic smem layout (tiles 128B-stride, SW128-swizzled) ----
static constexpr int SM_W3   = 0;                   // 64 floats (zero-padded)
static constexpr int SM_AH   = 1024;                // 128 rows x 128B (X hi)
static constexpr int SM_AL   = SM_AH  + 16384;      // X lo
static constexpr int SM_B1H  = SM_AL  + 16384;      // weight block: 4 x 8192 contiguous
static constexpr int SM_B1L  = SM_B1H + 8192;
static constexpr int SM_B2H  = SM_B1L + 8192;
static constexpr int SM_B2L  = SM_B2H + 8192;
static constexpr int SM_TOTAL = SM_B2L + 8192;      // 66560 B -> 3 CTAs/SM

DI uint32_t s2u(const void* p) {
    uint32_t a;
    asm("{ .reg .u64 t; cvta.to.shared.u64 t, %1; cvt.u32.u64 %0, t; }"
        : "=r"(a) : "l"(p));
    return a;
}
DI uint32_t swz(uint32_t off) { return off ^ ((off >> 3) & 0x70); }

DI float fsilu(float x) {
    float e, r;
    asm("ex2.approx.f32 %0, %1;" : "=f"(e) : "f"(x * -1.4426950408889634f));
    asm("rcp.approx.f32 %0, %1;" : "=f"(r) : "f"(e + 1.0f));
    return x * r;   // x * sigmoid(x)
}

// split v into bf16 hi + lo, store into two swizzled tiles at (row, col)
DI void st_split(char* hi, char* lo, int row, int k, float v) {
    __nv_bfloat16 h = __float2bfloat16(v);
    float hf = __bfloat162float(h);
    __nv_bfloat16 l = __float2bfloat16(v - hf);
    uint32_t off = swz((uint32_t)(row * 128 + k * 2));
    *reinterpret_cast<__nv_bfloat16*>(hi + off) = h;
    *reinterpret_cast<__nv_bfloat16*>(lo + off) = l;
}

// pack {lo=e, hi=o} floats -> bf16x2
DI uint32_t packbf(float e, float o) {
    uint32_t r;
    asm("cvt.rn.bf16x2.f32 %0, %1, %2;" : "=r"(r) : "f"(o), "f"(e));
    return r;
}
DI float bflo(uint32_t u) {
    __nv_bfloat162 p = *reinterpret_cast<__nv_bfloat162*>(&u);
    return __bfloat162float(p.x);
}
DI float bfhi(uint32_t u) {
    __nv_bfloat162 p = *reinterpret_cast<__nv_bfloat162*>(&u);
    return __bfloat162float(p.y);
}

// D[16x8] += A[16x16]*B[16x8] (bf16 in, f32 acc) -- sm_80 baseline HMMA
DI void mma16816(float* c, const uint32_t* a, uint32_t b0, uint32_t b1) {
    asm volatile(
        "mma.sync.aligned.m16n8k16.row.col.f32.bf16.bf16.f32 "
        "{%0,%1,%2,%3}, {%4,%5,%6,%7}, {%8,%9}, {%0,%1,%2,%3};"
        : "+f"(c[0]), "+f"(c[1]), "+f"(c[2]), "+f"(c[3])
        : "r"(a[0]), "r"(a[1]), "r"(a[2]), "r"(a[3]), "r"(b0), "r"(b1));
}

// ldmatrix x4 (sm_75 baseline)
DI void ldm4(uint32_t* r, uint32_t addr) {
    asm volatile("ldmatrix.sync.aligned.m8n8.x4.shared.b16 {%0,%1,%2,%3}, [%4];"
                 : "=r"(r[0]), "=r"(r[1]), "=r"(r[2]), "=r"(r[3]) : "r"(addr));
}

// ===================== prologue: build per-species weight tiles =====================
__global__ void __launch_bounds__(256)
prep_weights(const float* __restrict__ W1, const float* __restrict__ b1,
             const float* __restrict__ W2, const float* __restrict__ b2) {
    const int s = blockIdx.x, tid = threadIdx.x;
    char* B1H = reinterpret_cast<char*>(g_wt[s]);
    char* B1L = B1H + 8192;
    char* B2H = B1L + 8192;
    char* B2L = B2H + 8192;
    const float* W1s = W1 + (size_t)s * DIN * HID;
    const float* b1s = b1 + s * HID;
    const float* W2s = W2 + (size_t)s * HID * HID;
    const float* b2s = b2 + s * HID;

    // B1[n][k] = W1[k][n]; k==39 -> b1[n]; zero-pad to 64x64
    for (int idx = tid; idx < 64 * 64; idx += 256) {
        int n = idx >> 6, k = idx & 63;
        float v = 0.0f;
        if (n < HID) {
            if (k < DIN)       v = __ldg(W1s + k * HID + n);
            else if (k == DIN) v = __ldg(b1s + n);
        }
        st_split(B1H, B1L, n, k, v);
    }
    // B2[n][k] = W2[k][n]; k==50 -> b2[n]; zero-pad to 64x64
    for (int idx = tid; idx < 64 * 64; idx += 256) {
        int n = idx >> 6, k = idx & 63;
        float v = 0.0f;
        if (n < HID) {
            if (k < HID)       v = __ldg(W2s + k * HID + n);
            else if (k == HID) v = __ldg(b2s + n);
        }
        st_split(B2H, B2L, n, k, v);
    }
}

// ================================ main kernel ================================
__global__ void __launch_bounds__(256, 3)
atomic_mlp_kernel(const float* __restrict__ desc, const int* __restrict__ numbers,
                  const float* __restrict__ W3, const float* __restrict__ b3,
                  float* __restrict__ out) {
    extern __shared__ char smem[];
    const int tid = threadIdx.x, wid = tid >> 5, lid = tid & 31;
    const int g = lid >> 2, t = lid & 3;          // mma quad coords
    const int a = blockIdx.x, nb = blockIdx.y;
    const int warp_m = wid * 16;                  // each warp owns 16 rows

    const int s = __ldg(numbers + a);
    const float* W3s = W3 + s * HID;
    const float  b3v = __ldg(b3 + s);

    // ---- stage X: warp stages its own 16 rows (39 feats | 1.0 at 39 | zeros) ----
    {
        char* AH = smem + SM_AH; char* AL = smem + SM_AL;
        #pragma unroll 4
        for (int r = 0; r < 16; r++) {
            int row = warp_m + r;
            size_t n = (size_t)nb * 128 + row;
            const float* src = desc + (n * A_ATOMS + a) * DIN;
            float v0 = __ldg(src + lid);                           // lid < 39 always
            int k2 = lid + 32;
            float v1 = (k2 < DIN) ? __ldg(src + k2) : (k2 == DIN ? 1.0f : 0.0f);
            st_split(AH, AL, row, lid, v0);
            st_split(AH, AL, row, k2, v1);
        }
    }
    // ---- stage weights: straight 32KB copy of pre-swizzled tiles (L2-resident) ----
    {
        const uint4* src = reinterpret_cast<const uint4*>(g_wt[s]);
        uint4* dst = reinterpret_cast<uint4*>(smem + SM_B1H);
        #pragma unroll
        for (int i = 0; i < 8; i++)
            dst[tid + 256 * i] = __ldg(src + tid + 256 * i);
    }
    // ---- stage W3 (zero-padded to 64) ----
    if (tid < 64)
        reinterpret_cast<float*>(smem + SM_W3)[tid] = (tid < HID) ? __ldg(W3s + tid) : 0.0f;
    __syncthreads();   // only CTA-wide sync

    // ---- ldmatrix per-lane addressing (closed-form swizzle) ----
    const uint32_t sb = s2u(smem);
    const int lr = lid & 15, cb = lid >> 4, s7 = lr & 7;
    const uint32_t aAH = sb + SM_AH + (uint32_t)(warp_m + lr) * 128;
    const uint32_t aAL = sb + SM_AL + (uint32_t)(warp_m + lr) * 128;
    const uint32_t rB  = (uint32_t)lr * 128;

    // X hi fragments resident (3 ksteps)
    uint32_t Xh[3][4];
    #pragma unroll
    for (int ks = 0; ks < 3; ks++)
        ldm4(Xh[ks], aAH + ((((uint32_t)(2 * ks + cb)) ^ s7) << 4));

    uint32_t A2h[4][4], A2l[4][4];

    // ================= layer 1 (j-pair outer), repack into A2 =================
    #pragma unroll
    for (int jp = 0; jp < 4; jp++) {
        float acc0[4] = {0, 0, 0, 0}, acc1[4] = {0, 0, 0, 0};
        const uint32_t bH = sb + SM_B1H + (uint32_t)jp * 2048 + rB;
        const uint32_t bL = sb + SM_B1L + (uint32_t)jp * 2048 + rB;
        #pragma unroll
        for (int ks = 0; ks < 3; ks++) {
            uint32_t off = (((uint32_t)(2 * ks + cb)) ^ s7) << 4;
            uint32_t bh[4], bl[4], xl[4];
            ldm4(bh, bH + off);
            ldm4(bl, bL + off);
            ldm4(xl, aAL + off);
            mma16816(acc0, Xh[ks], bh[0], bh[2]);
            mma16816(acc0, xl,     bh[0], bh[2]);
            mma16816(acc0, Xh[ks], bl[0], bl[2]);
            if (jp < 3) {                              // j=7 (cols 56-63) dead
                mma16816(acc1, Xh[ks], bh[1], bh[3]);
                mma16816(acc1, xl,     bh[1], bh[3]);
                mma16816(acc1, Xh[ks], bl[1], bl[3]);
            }
        }
        // silu + bf16 split -> A2 fragment kstep jp (slots 0,1 = even j)
        float v0 = fsilu(acc0[0]), v1 = fsilu(acc0[1]);
        float v2 = fsilu(acc0[2]), v3 = fsilu(acc0[3]);
        if (jp == 3 && t == 1) { v0 = 1.0f; v1 = 0.0f; v2 = 1.0f; v3 = 0.0f; } // bias col 50
        uint32_t h0 = packbf(v0, v1), h1 = packbf(v2, v3);
        A2h[jp][0] = h0; A2l[jp][0] = packbf(v0 - bflo(h0), v1 - bfhi(h0));
        A2h[jp][1] = h1; A2l[jp][1] = packbf(v2 - bflo(h1), v3 - bfhi(h1));
        if (jp < 3) {                                  // slots 2,3 = odd j
            float u0 = fsilu(acc1[0]), u1 = fsilu(acc1[1]);
            float u2 = fsilu(acc1[2]), u3 = fsilu(acc1[3]);
            uint32_t h2 = packbf(u0, u1), h3 = packbf(u2, u3);
            A2h[jp][2] = h2; A2l[jp][2] = packbf(u0 - bflo(h2), u1 - bfhi(h2));
            A2h[jp][3] = h3; A2l[jp][3] = packbf(u2 - bflo(h3), u3 - bfhi(h3));
        } else {                                        // cols 56-63 = 0
            A2h[jp][2] = 0; A2h[jp][3] = 0; A2l[jp][2] = 0; A2l[jp][3] = 0;
        }
    }

    // ============ layer 2 (j-pair outer) with fused layer-3 dot ============
    const float* w3s = reinterpret_cast<const float*>(smem + SM_W3);
    float p0 = 0.0f, p1 = 0.0f;
    #pragma unroll
    for (int jp = 0; jp < 4; jp++) {
        float acc0[4] = {0, 0, 0, 0}, acc1[4] = {0, 0, 0, 0};
        const uint32_t bH = sb + SM_B2H + (uint32_t)jp * 2048 + rB;
        const uint32_t bL = sb + SM_B2L + (uint32_t)jp * 2048 + rB;
        #pragma unroll
        for (int ks = 0; ks < 4; ks++) {
            uint32_t off = (((uint32_t)(2 * ks + cb)) ^ s7) << 4;
            uint32_t bh[4], bl[4];
            ldm4(bh, bH + off);
            ldm4(bl, bL + off);
            mma16816(acc0, A2h[ks], bh[0], bh[2]);
            mma16816(acc0, A2l[ks], bh[0], bh[2]);
            mma16816(acc0, A2h[ks], bl[0], bl[2]);
            if (jp < 3) {
                mma16816(acc1, A2h[ks], bh[1], bh[3]);
                mma16816(acc1, A2l[ks], bh[1], bh[3]);
                mma16816(acc1, A2h[ks], bl[1], bl[3]);
            }
        }
        int c0 = 16 * jp + 2 * t;                      // even j cols
        float w0 = w3s[c0], w1 = w3s[c0 + 1];
        p0 = fmaf(fsilu(acc0[0]), w0, p0); p0 = fmaf(fsilu(acc0[1]), w1, p0);
        p1 = fmaf(fsilu(acc0[2]), w0, p1); p1 = fmaf(fsilu(acc0[3]), w1, p1);
        if (jp < 3) {
            int c1 = c0 + 8;                           // odd j cols
            float y0 = w3s[c1], y1 = w3s[c1 + 1];
            p0 = fmaf(fsilu(acc1[0]), y0, p0); p0 = fmaf(fsilu(acc1[1]), y1, p0);
            p1 = fmaf(fsilu(acc1[2]), y0, p1); p1 = fmaf(fsilu(acc1[3]), y1, p1);
        }
    }

    // reduce over t quads and store
    p0 += __shfl_xor_sync(0xffffffffu, p0, 1);
    p0 += __shfl_xor_sync(0xffffffffu, p0, 2);
    p1 += __shfl_xor_sync(0xffffffffu, p1, 1);
    p1 += __shfl_xor_sync(0xffffffffu, p1, 2);
    if (t == 0) {
        size_t n0 = (size_t)nb * 128 + warp_m + g;
        out[n0 * A_ATOMS + a]       = p0 + b3v;
        out[(n0 + 8) * A_ATOMS + a] = p1 + b3v;
    }
}

extern "C" void kernel_launch(void* const* d_in, const int* in_sizes, int n_in,
                              void* d_out, int out_size) {
    const float* desc    = (const float*)d_in[0];
    const int*   numbers = (const int*)  d_in[1];
    const float* W1      = (const float*)d_in[2];
    const float* b1      = (const float*)d_in[3];
    const float* W2      = (const float*)d_in[4];
    const float* b2      = (const float*)d_in[5];
    const float* W3      = (const float*)d_in[6];
    const float* b3      = (const float*)d_in[7];
    float* out           = (float*)d_out;

    prep_weights<<<NSPEC, 256>>>(W1, b1, W2, b2);

    cudaFuncSetAttribute(atomic_mlp_kernel,
                         cudaFuncAttributeMaxDynamicSharedMemorySize, SM_TOTAL);
    dim3 grid(A_ATOMS, 32);   // 256 atoms x 32 row-blocks of 128 samples
    atomic_mlp_kernel<<<grid, 256, SM_TOTAL>>>(desc, numbers, W3, b3, out);
}